// round 14
// baseline (speedup 1.0000x reference)
#include <cuda_runtime.h>
#include <cstdint>
#include <cstddef>

#define T_STEPS 4096
#define HD      512
#define NC      4880
#define G3      1536
#define SCAN_CTAS 32
#define NPKT    256           // 2 values per packet
#define GB      64            // gi staging batch (steps)

// ---------------- scratch (static device globals; no allocation) ----------------
__device__ float g_visit[(size_t)T_STEPS * HD];     // 8 MB
__device__ float g_gi[(size_t)T_STEPS * G3];        // 25 MB
__device__ float g_hs[(size_t)T_STEPS * HD];        // 8 MB (plain history for epilogue)
__device__ float g_ring[2][NPKT][32];               // 64 KB: 1 line per 2-value packet
__device__ float g_logits[T_STEPS];
__device__ float g_alpha[T_STEPS];

// ---------------- generic fp32 SIMT GEMM: C[M,N] = A x B (+bias) ----------------
template <bool A_KMAJ, bool B_KMAJ, bool BIAS>
__global__ __launch_bounds__(256)
void gemm_kernel(const float* __restrict__ A, const float* __restrict__ B,
                 const float* __restrict__ bias, float* __restrict__ C,
                 int M, int N, int K, int lda, int ldb, int ldc)
{
    constexpr int BM = 128, BN = 64, BK = 16;
    __shared__ float As[BK][BM + 4];
    __shared__ float Bs[BK][BN + 4];

    const int tid = threadIdx.x;
    const int tx  = tid & 15;
    const int ty  = tid >> 4;
    const int m0  = blockIdx.y * BM;
    const int n0  = blockIdx.x * BN;

    float acc[8][4];
#pragma unroll
    for (int i = 0; i < 8; i++)
#pragma unroll
        for (int j = 0; j < 4; j++) acc[i][j] = 0.f;

    for (int k0 = 0; k0 < K; k0 += BK) {
        if (A_KMAJ) {
#pragma unroll
            for (int it = 0; it < 2; it++) {
                int idx = tid + it * 256;
                int kk  = idx >> 5;
                int mm4 = idx & 31;
                float4 v = *(const float4*)&A[(size_t)(k0 + kk) * lda + m0 + mm4 * 4];
                *(float4*)&As[kk][mm4 * 4] = v;
            }
        } else {
#pragma unroll
            for (int it = 0; it < 2; it++) {
                int idx = tid + it * 256;
                int mm  = idx >> 2;
                int k4  = idx & 3;
                float4 v = *(const float4*)&A[(size_t)(m0 + mm) * lda + k0 + k4 * 4];
                As[k4 * 4 + 0][mm] = v.x;
                As[k4 * 4 + 1][mm] = v.y;
                As[k4 * 4 + 2][mm] = v.z;
                As[k4 * 4 + 3][mm] = v.w;
            }
        }
        if (B_KMAJ) {
            int kk  = tid >> 4;
            int nn4 = tid & 15;
            float4 v = *(const float4*)&B[(size_t)(k0 + kk) * ldb + n0 + nn4 * 4];
            *(float4*)&Bs[kk][nn4 * 4] = v;
        } else {
            int nn = tid >> 2;
            int k4 = tid & 3;
            float4 v = *(const float4*)&B[(size_t)(nn + n0) * ldb + k0 + k4 * 4];
            Bs[k4 * 4 + 0][nn] = v.x;
            Bs[k4 * 4 + 1][nn] = v.y;
            Bs[k4 * 4 + 2][nn] = v.z;
            Bs[k4 * 4 + 3][nn] = v.w;
        }
        __syncthreads();

#pragma unroll
        for (int kk = 0; kk < BK; kk++) {
            float4 a0 = *(const float4*)&As[kk][ty * 8];
            float4 a1 = *(const float4*)&As[kk][ty * 8 + 4];
            float4 b0 = *(const float4*)&Bs[kk][tx * 4];
            float a[8] = {a0.x, a0.y, a0.z, a0.w, a1.x, a1.y, a1.z, a1.w};
            float b[4] = {b0.x, b0.y, b0.z, b0.w};
#pragma unroll
            for (int i = 0; i < 8; i++)
#pragma unroll
                for (int j = 0; j < 4; j++) acc[i][j] += a[i] * b[j];
        }
        __syncthreads();
    }

    float4 bv = make_float4(0.f, 0.f, 0.f, 0.f);
    if (BIAS) bv = *(const float4*)&bias[n0 + tx * 4];
#pragma unroll
    for (int i = 0; i < 8; i++) {
        int m = m0 + ty * 8 + i;
        float4 v;
        v.x = acc[i][0] + bv.x;
        v.y = acc[i][1] + bv.y;
        v.z = acc[i][2] + bv.z;
        v.w = acc[i][3] + bv.w;
        *(float4*)&C[(size_t)m * ldc + n0 + tx * 4] = v;
    }
}

// ---------------- reset ring epochs (every replay) ----------------
__global__ __launch_bounds__(1024)
void ring_reset_kernel()
{
    int i = blockIdx.x * 1024 + threadIdx.x;   // grid covers 2*NPKT*32 floats
    ((float*)g_ring)[i] = 0.f;
}

// ---------------- volatile / math helpers ----------------
__device__ __forceinline__ float4 ldv4(const float* p)
{
    float4 v;
    asm volatile("ld.volatile.global.v4.f32 {%0,%1,%2,%3}, [%4];"
                 : "=f"(v.x), "=f"(v.y), "=f"(v.z), "=f"(v.w) : "l"(p) : "memory");
    return v;
}
__device__ __forceinline__ void stv4(float* p, float a, float b, float c, float d)
{
    asm volatile("st.volatile.global.v4.f32 [%0], {%1,%2,%3,%4};"
                 :: "l"(p), "f"(a), "f"(b), "f"(c), "f"(d) : "memory");
}
__device__ __forceinline__ void fma2(unsigned long long& acc,
                                     unsigned long long a, unsigned long long b)
{
    asm("fma.rn.f32x2 %0, %1, %2, %0;" : "+l"(acc) : "l"(a), "l"(b));
}
__device__ __forceinline__ float2 unpk(unsigned long long v)
{
    return *reinterpret_cast<float2*>(&v);
}
__device__ __forceinline__ float tanh_fast(float x)
{
    float e = __expf(2.f * x);
    return 1.f - 2.f / (e + 1.f);
}

// ---------------- GRU scan v12: v11 + SMEM-staged gi (clean poll queue) -------
// Warp w of CTA c owns jA=16c+2w, jB=jA+1 (6 W_hh rows in regs as f32x2).
// gi is staged: every 64 steps the CTA bulk-loads its 64x48-float slice into
// SMEM (coalesced). Per step the ONLY global load issued before the poll is
// nothing — the poll is the first memory op of the step, so its completion
// isn't queued behind DRAM-latency gi loads in the per-SM L1tex FIFO
// (loads complete in issue order). gi comes from broadcast LDS afterward.
__global__ __launch_bounds__(256)
void gru_scan12_kernel(const float* __restrict__ W_hh, const float* __restrict__ b_hh,
                       const float* __restrict__ gi)
{
    __shared__ float h_s[2][HD];
    __shared__ float gi_s[GB * 48];      // 12 KB: 64 steps x (3 gates x 16 j)

    const int tid  = threadIdx.x;
    const int w    = tid >> 5;
    const int lane = tid & 31;
    const int c    = blockIdx.x;
    const int jA   = c * 16 + 2 * w;
    const int jB   = jA + 1;
    const int pkt  = c * 8 + w;          // this warp's packet index

    // --- weights into registers: 2 indices x 3 gates x 16 elems, f32x2 packed ---
    unsigned long long wAr[8], wAz[8], wAn[8], wBr[8], wBz[8], wBn[8];
    {
        const unsigned long long* pAr =
            (const unsigned long long*)(W_hh + (size_t)jA * HD + lane * 16);
        const unsigned long long* pAz =
            (const unsigned long long*)(W_hh + (size_t)(HD + jA) * HD + lane * 16);
        const unsigned long long* pAn =
            (const unsigned long long*)(W_hh + (size_t)(2 * HD + jA) * HD + lane * 16);
        const unsigned long long* pBr =
            (const unsigned long long*)(W_hh + (size_t)jB * HD + lane * 16);
        const unsigned long long* pBz =
            (const unsigned long long*)(W_hh + (size_t)(HD + jB) * HD + lane * 16);
        const unsigned long long* pBn =
            (const unsigned long long*)(W_hh + (size_t)(2 * HD + jB) * HD + lane * 16);
#pragma unroll
        for (int q = 0; q < 8; q++) {
            wAr[q] = pAr[q]; wAz[q] = pAz[q]; wAn[q] = pAn[q];
            wBr[q] = pBr[q]; wBz[q] = pBz[q]; wBn[q] = pBn[q];
        }
    }
    // biases on all lanes (broadcast loads)
    const float bArh = __ldg(b_hh + jA);
    const float bAzh = __ldg(b_hh + HD + jA);
    const float bAnh = __ldg(b_hh + 2 * HD + jA);
    const float bBrh = __ldg(b_hh + jB);
    const float bBzh = __ldg(b_hh + HD + jB);
    const float bBnh = __ldg(b_hh + 2 * HD + jB);

    // zero initial-state buffer (t=0 reads buf 0)
    h_s[0][tid]       = 0.f;
    h_s[0][tid + 256] = 0.f;
    __syncthreads();

    for (int t = 0; t < T_STEPS; t++) {
        const int buf = t & 1;

        // --- stage next 64 steps of gi into SMEM (every 64 steps) ---
        if ((t & (GB - 1)) == 0) {
#pragma unroll
            for (int it = 0; it < 12; it++) {
                int idx = it * 256 + tid;            // 0..3071
                int s   = idx / 48;
                int rem = idx - s * 48;
                int g   = rem >> 4;                  // gate 0..2
                int jj  = rem & 15;                  // j - 16c
                gi_s[idx] = gi[(size_t)(t + s) * G3 + g * HD + c * 16 + jj];
            }
            if (t == 0) __syncthreads();   // t>0: covered by the post-poll barrier
        }

        if (t > 0) {
            // FIRST memory op of the step: poll this thread's packet of h_{t-1}
            const float* lp = &g_ring[(t - 1) & 1][tid][0];
            float4 pk = ldv4(lp);
            while (__float_as_uint(pk.z) != (unsigned)t) pk = ldv4(lp);
            h_s[buf][2 * tid]     = pk.x;
            h_s[buf][2 * tid + 1] = pk.y;
            __syncthreads();               // also publishes gi_s when staged
        }

        // per-step gi from SMEM (broadcast LDS, same addr across lanes)
        const float* gs = &gi_s[(t & (GB - 1)) * 48];
        const float gAr = gs[2 * w],      gBr = gs[2 * w + 1];
        const float gAz = gs[16 + 2 * w], gBz = gs[16 + 2 * w + 1];
        const float gAn = gs[32 + 2 * w], gBn = gs[32 + 2 * w + 1];

        // --- six 512-dots (2 idx x 3 gates), 16 h elems per lane, f32x2 ---
        unsigned long long aAr = 0ull, aAz = 0ull, aAn = 0ull;
        unsigned long long aBr = 0ull, aBz = 0ull, aBn = 0ull;
        const unsigned long long* hp =
            (const unsigned long long*)&h_s[buf][lane * 16];
#pragma unroll
        for (int q = 0; q < 8; q++) {
            unsigned long long hv = hp[q];
            fma2(aAr, wAr[q], hv);
            fma2(aAz, wAz[q], hv);
            fma2(aAn, wAn[q], hv);
            fma2(aBr, wBr[q], hv);
            fma2(aBz, wBz[q], hv);
            fma2(aBn, wBn[q], hv);
        }
        float2 uAr = unpk(aAr), uAz = unpk(aAz), uAn = unpk(aAn);
        float2 uBr = unpk(aBr), uBz = unpk(aBz), uBn = unpk(aBn);
        float sAr = uAr.x + uAr.y, sAz = uAz.x + uAz.y, sAn = uAn.x + uAn.y;
        float sBr = uBr.x + uBr.y, sBz = uBz.x + uBz.y, sBn = uBn.x + uBn.y;

        // 5-level butterfly on 6 independent accumulators
#pragma unroll
        for (int o = 16; o > 0; o >>= 1) {
            sAr += __shfl_xor_sync(0xffffffffu, sAr, o);
            sAz += __shfl_xor_sync(0xffffffffu, sAz, o);
            sAn += __shfl_xor_sync(0xffffffffu, sAn, o);
            sBr += __shfl_xor_sync(0xffffffffu, sBr, o);
            sBz += __shfl_xor_sync(0xffffffffu, sBz, o);
            sBn += __shfl_xor_sync(0xffffffffu, sBn, o);
        }

        // gates on all lanes (broadcast LDS for h_prev[jA], h_prev[jB])
        float hjA = h_s[buf][jA];
        float hjB = h_s[buf][jB];
        float rA  = 1.f / (1.f + __expf(-(gAr + sAr + bArh)));
        float zA  = 1.f / (1.f + __expf(-(gAz + sAz + bAzh)));
        float nA  = tanh_fast(gAn + rA * (sAn + bAnh));
        float hnA = (1.f - zA) * nA + zA * hjA;
        float rB  = 1.f / (1.f + __expf(-(gBr + sBr + bBrh)));
        float zB  = 1.f / (1.f + __expf(-(gBz + sBz + bBzh)));
        float nB  = tanh_fast(gBn + rB * (sBn + bBnh));
        float hnB = (1.f - zB) * nB + zB * hjB;

        if (lane == 0) {
            // single self-flagging packet: (hA, hB, epoch=t+1, 0)
            stv4(&g_ring[t & 1][pkt][0], hnA, hnB,
                 __uint_as_float((unsigned)(t + 1)), 0.f);
            // plain history store for the epilogue (off critical path)
            *(float2*)&g_hs[(size_t)t * HD + jA] = make_float2(hnA, hnB);
        }
    }
}

// ---------------- logits[t] = dot(hs[t], w_att) ----------------
__global__ __launch_bounds__(256)
void logits_kernel(const float* __restrict__ w_att)
{
    __shared__ float watt[HD];
    const int tid  = threadIdx.x;
    const int w    = tid >> 5;
    const int lane = tid & 31;
    watt[tid]       = w_att[tid];
    watt[tid + 256] = w_att[tid + 256];
    __syncthreads();

    int t = blockIdx.x * 8 + w;
    const float* h = g_hs + (size_t)t * HD;
    float acc = 0.f;
    int base = lane * 16;
#pragma unroll
    for (int i = 0; i < 16; i += 4) {
        float4 hv = *(const float4*)&h[base + i];
        float4 wv = *(const float4*)&watt[base + i];
        acc += hv.x * wv.x + hv.y * wv.y + hv.z * wv.z + hv.w * wv.w;
    }
#pragma unroll
    for (int off = 16; off > 0; off >>= 1)
        acc += __shfl_down_sync(0xffffffffu, acc, off);
    if (lane == 0) g_logits[t] = acc;
}

// ---------------- softmax over 4096 logits; also zero d_out ----------------
__global__ __launch_bounds__(1024)
void softmax_kernel(float* __restrict__ out)
{
    __shared__ float red[32];
    const int tid  = threadIdx.x;
    const int lane = tid & 31;
    const int wrp  = tid >> 5;

    float m = -1e30f;
    for (int i = tid; i < T_STEPS; i += 1024) m = fmaxf(m, g_logits[i]);
#pragma unroll
    for (int o = 16; o > 0; o >>= 1) m = fmaxf(m, __shfl_xor_sync(0xffffffffu, m, o));
    if (lane == 0) red[wrp] = m;
    __syncthreads();
    if (wrp == 0) {
        float v = red[lane];
#pragma unroll
        for (int o = 16; o > 0; o >>= 1) v = fmaxf(v, __shfl_xor_sync(0xffffffffu, v, o));
        if (lane == 0) red[0] = v;
    }
    __syncthreads();
    m = red[0];
    __syncthreads();

    float s = 0.f;
    for (int i = tid; i < T_STEPS; i += 1024) {
        float e = __expf(g_logits[i] - m);
        g_alpha[i] = e;
        s += e;
    }
#pragma unroll
    for (int o = 16; o > 0; o >>= 1) s += __shfl_xor_sync(0xffffffffu, s, o);
    if (lane == 0) red[wrp] = s;
    __syncthreads();
    if (wrp == 0) {
        float v = red[lane];
#pragma unroll
        for (int o = 16; o > 0; o >>= 1) v += __shfl_xor_sync(0xffffffffu, v, o);
        if (lane == 0) red[0] = v;
    }
    __syncthreads();
    float inv = 1.f / red[0];
    for (int i = tid; i < T_STEPS; i += 1024) g_alpha[i] *= inv;

    if (tid < HD) out[tid] = 0.f;
}

// ---------------- out[d] += sum_t alpha[t] * hs[t][d] ----------------
__global__ __launch_bounds__(256)
void wsum_kernel(float* __restrict__ out)
{
    const int tid = threadIdx.x;
    const int d   = tid * 2;
    float ax = 0.f, ay = 0.f;
    int t0 = blockIdx.x * 64;
#pragma unroll 4
    for (int tt = 0; tt < 64; tt++) {
        int t = t0 + tt;
        float a = g_alpha[t];
        float2 hv = *(const float2*)&g_hs[(size_t)t * HD + d];
        ax += a * hv.x;
        ay += a * hv.y;
    }
    atomicAdd(out + d, ax);
    atomicAdd(out + d + 1, ay);
}

// ---------------- launcher ----------------
extern "C" void kernel_launch(void* const* d_in, const int* in_sizes, int n_in,
                              void* d_out, int out_size)
{
    const float* H     = (const float*)d_in[0];
    // d_in[1] = TE (unused)
    const float* X_emb = (const float*)d_in[2];
    const float* W_ih  = (const float*)d_in[3];
    const float* W_hh  = (const float*)d_in[4];
    const float* b_ih  = (const float*)d_in[5];
    const float* b_hh  = (const float*)d_in[6];
    const float* w_att = (const float*)d_in[7];
    float* out = (float*)d_out;

    float* visit; float* gi;
    cudaGetSymbolAddress((void**)&visit, g_visit);
    cudaGetSymbolAddress((void**)&gi, g_gi);

    // 0) reset the epoch ring (64 KB)
    ring_reset_kernel<<<(2 * NPKT * 32) / 1024, 1024>>>();
    // 1) visit_emb[4096,512] = H^T @ X_emb
    {
        dim3 grid(HD / 64, T_STEPS / 128);
        gemm_kernel<true, true, false><<<grid, 256>>>(
            H, X_emb, nullptr, visit, T_STEPS, HD, NC, T_STEPS, HD, HD);
    }
    // 2) gi[4096,1536] = visit_emb @ W_ih^T + b_ih
    {
        dim3 grid(G3 / 64, T_STEPS / 128);
        gemm_kernel<false, false, true><<<grid, 256>>>(
            visit, W_ih, b_ih, gi, T_STEPS, G3, HD, HD, HD, G3);
    }
    // 3) sequential GRU scan (clean poll queue: gi staged in SMEM)
    gru_scan12_kernel<<<SCAN_CTAS, 256>>>(W_hh, b_hh, gi);
    // 4) attention logits
    logits_kernel<<<T_STEPS / 8, 256>>>(w_att);
    // 5) softmax (+ zero out)
    softmax_kernel<<<1, 1024>>>(out);
    // 6) weighted sum
    wsum_kernel<<<T_STEPS / 64, 256>>>(out);
}

// round 17
// speedup vs baseline: 1.0571x; 1.0571x over previous
#include <cuda_runtime.h>
#include <cstdint>
#include <cstddef>

#define T_STEPS 4096
#define HD      512
#define NC      4880
#define G3      1536

// ---------------- scratch (static device globals; no allocation) ----------------
__device__ float g_visit[(size_t)T_STEPS * HD];     // 8 MB
__device__ float g_gi[(size_t)T_STEPS * G3];        // 25 MB
__device__ float g_hs[(size_t)T_STEPS * HD];        // 8 MB (plain history for epilogue)
__device__ float g_hring[2][HD][32];                // 128 KB comm ring: 1 line per value
__device__ float g_logits[T_STEPS];
__device__ float g_alpha[T_STEPS];

// ---------------- packed f32x2 helpers ----------------
typedef unsigned long long ull;
__device__ __forceinline__ void fma2(ull& acc, ull a, ull b)
{
    asm("fma.rn.f32x2 %0, %1, %2, %0;" : "+l"(acc) : "l"(a), "l"(b));
}
__device__ __forceinline__ ull pk2(float x, float y)
{
    ull r;
    asm("mov.b64 %0, {%1, %2};" : "=l"(r) : "f"(x), "f"(y));
    return r;
}
__device__ __forceinline__ float2 unpk(ull v)
{
    return *reinterpret_cast<float2*>(&v);
}

// ---------------- fp32 SIMT GEMM with f32x2-packed microtile ----------------
// C[M,N] = A x B (+bias). Microtile 8x4 per thread held as 4x4 row-pair f32x2
// accumulators: 16 FFMA2 + 4 dup-packs + 3 LDS.128 per k-slice (vs 32 scalar
// FFMA) -> ~1.5x issue throughput. Each half of an f32x2 is an independent
// fma chain => per-element accumulation order identical to the scalar version.
template <bool A_KMAJ, bool B_KMAJ, bool BIAS>
__global__ __launch_bounds__(256)
void gemm_kernel(const float* __restrict__ A, const float* __restrict__ B,
                 const float* __restrict__ bias, float* __restrict__ C,
                 int M, int N, int K, int lda, int ldb, int ldc)
{
    constexpr int BM = 128, BN = 64, BK = 16;
    __shared__ float As[BK][BM + 4];
    __shared__ float Bs[BK][BN + 4];

    const int tid = threadIdx.x;
    const int tx  = tid & 15;
    const int ty  = tid >> 4;
    const int m0  = blockIdx.y * BM;
    const int n0  = blockIdx.x * BN;

    ull accp[4][4];   // row-pair (2r,2r+1) x col j accumulators
#pragma unroll
    for (int r = 0; r < 4; r++)
#pragma unroll
        for (int j = 0; j < 4; j++) accp[r][j] = 0ull;

    for (int k0 = 0; k0 < K; k0 += BK) {
        if (A_KMAJ) {
#pragma unroll
            for (int it = 0; it < 2; it++) {
                int idx = tid + it * 256;
                int kk  = idx >> 5;
                int mm4 = idx & 31;
                float4 v = *(const float4*)&A[(size_t)(k0 + kk) * lda + m0 + mm4 * 4];
                *(float4*)&As[kk][mm4 * 4] = v;
            }
        } else {
#pragma unroll
            for (int it = 0; it < 2; it++) {
                int idx = tid + it * 256;
                int mm  = idx >> 2;
                int k4  = idx & 3;
                float4 v = *(const float4*)&A[(size_t)(m0 + mm) * lda + k0 + k4 * 4];
                As[k4 * 4 + 0][mm] = v.x;
                As[k4 * 4 + 1][mm] = v.y;
                As[k4 * 4 + 2][mm] = v.z;
                As[k4 * 4 + 3][mm] = v.w;
            }
        }
        if (B_KMAJ) {
            int kk  = tid >> 4;
            int nn4 = tid & 15;
            float4 v = *(const float4*)&B[(size_t)(k0 + kk) * ldb + n0 + nn4 * 4];
            *(float4*)&Bs[kk][nn4 * 4] = v;
        } else {
            int nn = tid >> 2;
            int k4 = tid & 3;
            float4 v = *(const float4*)&B[(size_t)(nn + n0) * ldb + k0 + k4 * 4];
            Bs[k4 * 4 + 0][nn] = v.x;
            Bs[k4 * 4 + 1][nn] = v.y;
            Bs[k4 * 4 + 2][nn] = v.z;
            Bs[k4 * 4 + 3][nn] = v.w;
        }
        __syncthreads();

#pragma unroll
        for (int kk = 0; kk < BK; kk++) {
            // A row-pairs: adjacent m values adjacent in As -> direct 8B reads
            const ull* apk = (const ull*)&As[kk][ty * 8];   // 4 packed pairs
            ull ap0 = apk[0], ap1 = apk[1], ap2 = apk[2], ap3 = apk[3];
            float4 b0 = *(const float4*)&Bs[kk][tx * 4];
            ull bp0 = pk2(b0.x, b0.x);
            ull bp1 = pk2(b0.y, b0.y);
            ull bp2 = pk2(b0.z, b0.z);
            ull bp3 = pk2(b0.w, b0.w);
            fma2(accp[0][0], ap0, bp0); fma2(accp[0][1], ap0, bp1);
            fma2(accp[0][2], ap0, bp2); fma2(accp[0][3], ap0, bp3);
            fma2(accp[1][0], ap1, bp0); fma2(accp[1][1], ap1, bp1);
            fma2(accp[1][2], ap1, bp2); fma2(accp[1][3], ap1, bp3);
            fma2(accp[2][0], ap2, bp0); fma2(accp[2][1], ap2, bp1);
            fma2(accp[2][2], ap2, bp2); fma2(accp[2][3], ap2, bp3);
            fma2(accp[3][0], ap3, bp0); fma2(accp[3][1], ap3, bp1);
            fma2(accp[3][2], ap3, bp2); fma2(accp[3][3], ap3, bp3);
        }
        __syncthreads();
    }

    float4 bv = make_float4(0.f, 0.f, 0.f, 0.f);
    if (BIAS) bv = *(const float4*)&bias[n0 + tx * 4];
#pragma unroll
    for (int r = 0; r < 4; r++) {
        float2 c0 = unpk(accp[r][0]);
        float2 c1 = unpk(accp[r][1]);
        float2 c2 = unpk(accp[r][2]);
        float2 c3 = unpk(accp[r][3]);
        int mlo = m0 + ty * 8 + 2 * r;
        float4 vlo = make_float4(c0.x + bv.x, c1.x + bv.y, c2.x + bv.z, c3.x + bv.w);
        float4 vhi = make_float4(c0.y + bv.x, c1.y + bv.y, c2.y + bv.z, c3.y + bv.w);
        *(float4*)&C[(size_t)mlo * ldc + n0 + tx * 4]       = vlo;
        *(float4*)&C[(size_t)(mlo + 1) * ldc + n0 + tx * 4] = vhi;
    }
}

// ---------------- reset ring epochs ----------------
__global__ __launch_bounds__(1024)
void ring_reset_kernel()
{
    int i = blockIdx.x * 1024 + threadIdx.x;   // grid covers 2*HD*32 floats
    ((float*)g_hring)[i] = 0.f;
}

// ---------------- volatile helpers ----------------
__device__ __forceinline__ float2 ldv2(const float* p)
{
    float2 v;
    asm volatile("ld.volatile.global.v2.f32 {%0,%1}, [%2];"
                 : "=f"(v.x), "=f"(v.y) : "l"(p) : "memory");
    return v;
}
__device__ __forceinline__ void stv2(float* p, float a, float b)
{
    asm volatile("st.volatile.global.v2.f32 [%0], {%1,%2};"
                 :: "l"(p), "f"(a), "f"(b) : "memory");
}

// ---------------- GRU scan v5 (CHAMPION — unchanged): 64 CTAs x 8 warps -------
// Warp (bid, w) owns hidden index j = bid*8 + w; its 3 W_hh rows live in
// registers (48 floats/lane). h[t][j] published as (value, epoch=t+1) in its
// OWN 128B line of a depth-2 ring; thread tid polls its own 2 packets.
__global__ __launch_bounds__(256)
void gru_scan5_kernel(const float* __restrict__ W_hh, const float* __restrict__ b_hh,
                      const float* __restrict__ gi)
{
    __shared__ float h_s[2][HD];

    const int tid  = threadIdx.x;
    const int w    = tid >> 5;
    const int lane = tid & 31;
    const int j    = blockIdx.x * 8 + w;
    const int d    = tid * 2;               // this thread's pair of h values

    // --- weights into registers (once) ---
    float4 wr4[4], wz4[4], wn4[4];
    {
        const float4* pr = (const float4*)(W_hh + (size_t)j * HD)            + lane * 4;
        const float4* pz = (const float4*)(W_hh + (size_t)(HD + j) * HD)     + lane * 4;
        const float4* pn = (const float4*)(W_hh + (size_t)(2 * HD + j) * HD) + lane * 4;
#pragma unroll
        for (int q = 0; q < 4; q++) { wr4[q] = pr[q]; wz4[q] = pz[q]; wn4[q] = pn[q]; }
    }
    float bhr = 0.f, bhz = 0.f, bhn = 0.f;
    if (lane == 0) {
        bhr = b_hh[j];
        bhz = b_hh[HD + j];
        bhn = b_hh[2 * HD + j];
    }

    // zero initial-state buffer (t=0 reads buf 0)
    h_s[0][d]     = 0.f;
    h_s[0][d + 1] = 0.f;

    // gi prefetch for t=0 (lane0)
    float gr = 0.f, gz = 0.f, gn = 0.f;
    if (lane == 0) {
        gr = __ldg(gi + j);
        gz = __ldg(gi + HD + j);
        gn = __ldg(gi + 2 * HD + j);
    }
    __syncthreads();

    float hj = 0.f;   // h_{t-1}[j], carried in-register

    for (int t = 0; t < T_STEPS; t++) {
        const int buf = t & 1;

        // issue next step's gi loads early (complete during poll/compute)
        float grn = 0.f, gzn = 0.f, gnn = 0.f;
        if (lane == 0 && t + 1 < T_STEPS) {
            const float* gt = gi + (size_t)(t + 1) * G3;
            grn = __ldg(gt + j);
            gzn = __ldg(gt + HD + j);
            gnn = __ldg(gt + 2 * HD + j);
        }

        if (t > 0) {
            // poll this thread's 2 values of h_{t-1}; expect epoch == t
            const unsigned want = (unsigned)t;
            const int s = (t - 1) & 1;
            const float* p0 = &g_hring[s][d][0];
            const float* p1 = &g_hring[s][d + 1][0];
            float2 a = ldv2(p0);
            float2 b = ldv2(p1);
            while (__float_as_uint(a.y) != want) a = ldv2(p0);
            while (__float_as_uint(b.y) != want) b = ldv2(p1);
            h_s[buf][d]     = a.x;
            h_s[buf][d + 1] = b.x;
            __syncthreads();
        }

        // --- three 512-dots, 16 h elems per lane from SMEM, weights in regs ---
        float ar = 0.f, az = 0.f, an = 0.f;
#pragma unroll
        for (int q = 0; q < 4; q++) {
            float4 hv = *(const float4*)&h_s[buf][lane * 16 + q * 4];
            ar += hv.x * wr4[q].x + hv.y * wr4[q].y + hv.z * wr4[q].z + hv.w * wr4[q].w;
            az += hv.x * wz4[q].x + hv.y * wz4[q].y + hv.z * wz4[q].z + hv.w * wz4[q].w;
            an += hv.x * wn4[q].x + hv.y * wn4[q].y + hv.z * wn4[q].z + hv.w * wn4[q].w;
        }
#pragma unroll
        for (int o = 16; o > 0; o >>= 1) {
            ar += __shfl_xor_sync(0xffffffffu, ar, o);
            az += __shfl_xor_sync(0xffffffffu, az, o);
            an += __shfl_xor_sync(0xffffffffu, an, o);
        }

        if (lane == 0) {
            if (t > 0) hj = h_s[buf][j];
            float r  = 1.f / (1.f + __expf(-(gr + ar + bhr)));
            float z  = 1.f / (1.f + __expf(-(gz + az + bhz)));
            float nv = tanhf(gn + r * (an + bhn));
            float hn = (1.f - z) * nv + z * hj;
            // publish (value, epoch=t+1) as one 8B packet in j's own line
            stv2(&g_hring[t & 1][j][0], hn, __uint_as_float((unsigned)(t + 1)));
            // plain history store for the epilogue (off critical path)
            g_hs[(size_t)t * HD + j] = hn;
            hj = hn;
        }

        gr = grn; gz = gzn; gn = gnn;
    }
}

// ---------------- logits[t] = dot(hs[t], w_att) ----------------
__global__ __launch_bounds__(256)
void logits_kernel(const float* __restrict__ w_att)
{
    __shared__ float watt[HD];
    const int tid  = threadIdx.x;
    const int w    = tid >> 5;
    const int lane = tid & 31;
    watt[tid]       = w_att[tid];
    watt[tid + 256] = w_att[tid + 256];
    __syncthreads();

    int t = blockIdx.x * 8 + w;
    const float* h = g_hs + (size_t)t * HD;
    float acc = 0.f;
    int base = lane * 16;
#pragma unroll
    for (int i = 0; i < 16; i += 4) {
        float4 hv = *(const float4*)&h[base + i];
        float4 wv = *(const float4*)&watt[base + i];
        acc += hv.x * wv.x + hv.y * wv.y + hv.z * wv.z + hv.w * wv.w;
    }
#pragma unroll
    for (int off = 16; off > 0; off >>= 1)
        acc += __shfl_down_sync(0xffffffffu, acc, off);
    if (lane == 0) g_logits[t] = acc;
}

// ---------------- softmax over 4096 logits; also zero d_out ----------------
__global__ __launch_bounds__(1024)
void softmax_kernel(float* __restrict__ out)
{
    __shared__ float red[32];
    const int tid  = threadIdx.x;
    const int lane = tid & 31;
    const int wrp  = tid >> 5;

    float m = -1e30f;
    for (int i = tid; i < T_STEPS; i += 1024) m = fmaxf(m, g_logits[i]);
#pragma unroll
    for (int o = 16; o > 0; o >>= 1) m = fmaxf(m, __shfl_xor_sync(0xffffffffu, m, o));
    if (lane == 0) red[wrp] = m;
    __syncthreads();
    if (wrp == 0) {
        float v = red[lane];
#pragma unroll
        for (int o = 16; o > 0; o >>= 1) v = fmaxf(v, __shfl_xor_sync(0xffffffffu, v, o));
        if (lane == 0) red[0] = v;
    }
    __syncthreads();
    m = red[0];
    __syncthreads();

    float s = 0.f;
    for (int i = tid; i < T_STEPS; i += 1024) {
        float e = __expf(g_logits[i] - m);
        g_alpha[i] = e;
        s += e;
    }
#pragma unroll
    for (int o = 16; o > 0; o >>= 1) s += __shfl_xor_sync(0xffffffffu, s, o);
    if (lane == 0) red[wrp] = s;
    __syncthreads();
    if (wrp == 0) {
        float v = red[lane];
#pragma unroll
        for (int o = 16; o > 0; o >>= 1) v += __shfl_xor_sync(0xffffffffu, v, o);
        if (lane == 0) red[0] = v;
    }
    __syncthreads();
    float inv = 1.f / red[0];
    for (int i = tid; i < T_STEPS; i += 1024) g_alpha[i] *= inv;

    if (tid < HD) out[tid] = 0.f;
}

// ---------------- out[d] += sum_t alpha[t] * hs[t][d] ----------------
__global__ __launch_bounds__(256)
void wsum_kernel(float* __restrict__ out)
{
    const int tid = threadIdx.x;
    const int d   = tid * 2;
    float ax = 0.f, ay = 0.f;
    int t0 = blockIdx.x * 64;
#pragma unroll 4
    for (int tt = 0; tt < 64; tt++) {
        int t = t0 + tt;
        float a = g_alpha[t];
        float2 hv = *(const float2*)&g_hs[(size_t)t * HD + d];
        ax += a * hv.x;
        ay += a * hv.y;
    }
    atomicAdd(out + d, ax);
    atomicAdd(out + d + 1, ay);
}

// ---------------- launcher ----------------
extern "C" void kernel_launch(void* const* d_in, const int* in_sizes, int n_in,
                              void* d_out, int out_size)
{
    const float* H     = (const float*)d_in[0];
    // d_in[1] = TE (unused)
    const float* X_emb = (const float*)d_in[2];
    const float* W_ih  = (const float*)d_in[3];
    const float* W_hh  = (const float*)d_in[4];
    const float* b_ih  = (const float*)d_in[5];
    const float* b_hh  = (const float*)d_in[6];
    const float* w_att = (const float*)d_in[7];
    float* out = (float*)d_out;

    float* visit; float* gi;
    cudaGetSymbolAddress((void**)&visit, g_visit);
    cudaGetSymbolAddress((void**)&gi, g_gi);

    // 0) reset the epoch ring (128 KB)
    ring_reset_kernel<<<(2 * HD * 32) / 1024, 1024>>>();
    // 1) visit_emb[4096,512] = H^T @ X_emb
    {
        dim3 grid(HD / 64, T_STEPS / 128);
        gemm_kernel<true, true, false><<<grid, 256>>>(
            H, X_emb, nullptr, visit, T_STEPS, HD, NC, T_STEPS, HD, HD);
    }
    // 2) gi[4096,1536] = visit_emb @ W_ih^T + b_ih
    {
        dim3 grid(G3 / 64, T_STEPS / 128);
        gemm_kernel<false, false, true><<<grid, 256>>>(
            visit, W_ih, b_ih, gi, T_STEPS, G3, HD, HD, HD, G3);
    }
    // 3) sequential GRU scan (champion v5: line-per-value epoch ring, 64 CTAs)
    gru_scan5_kernel<<<64, 256>>>(W_hh, b_hh, gi);
    // 4) attention logits
    logits_kernel<<<T_STEPS / 8, 256>>>(w_att);
    // 5) softmax (+ zero out)
    softmax_kernel<<<1, 1024>>>(out);
    // 6) weighted sum
    wsum_kernel<<<T_STEPS / 64, 256>>>(out);
}